// round 9
// baseline (speedup 1.0000x reference)
#include <cuda_runtime.h>
#include <cstdint>

#define N_Q 16384
#define M_R 16384
#define TPB 256
#define QPT 2           // 2 queries/thread -> ~70 regs -> occ 3
#define JS  13          // 32 x 13 = 416 CTAs <= 444 slots @ occ 3 (single wave)
#define TJ  128         // js per smem tile
typedef unsigned long long u64;

__device__ u64 g_c2[M_R];      // packed {c_j, 0}
__device__ u64 g_best[N_Q];    // packed (sortable key | ~j)

static __device__ __forceinline__ u64 ffma2(u64 a, u64 b, u64 c) {
    u64 d;
    asm("fma.rn.f32x2 %0, %1, %2, %3;" : "=l"(d) : "l"(a), "l"(b), "l"(c));
    return d;
}
static __device__ __forceinline__ u64 pack2(float lo, float hi) {
    u64 d;
    asm("mov.b64 %0, {%1, %2};" : "=l"(d) : "f"(lo), "f"(hi));
    return d;
}
static __device__ __forceinline__ void unpack2(u64 v, float& lo, float& hi) {
    asm("mov.b64 {%0, %1}, %2;" : "=f"(lo), "=f"(hi) : "l"(v));
}
static __device__ __forceinline__ u64 enc(float s, int j) {
    uint32_t u = __float_as_uint(s);
    uint32_t key = (u & 0x80000000u) ? ~u : (u | 0x80000000u);  // monotone f32 -> u32
    return ((u64)key << 32) | (uint32_t)(~j);                   // tie -> smaller j wins
}

// ---- prep: bias {c,0}, reset accumulators ----
__global__ void prep_kernel(const float* __restrict__ xb) {
    int j = blockIdx.x * blockDim.x + threadIdx.x;
    if (j >= M_R) return;
    const float4* r = (const float4*)(xb + (size_t)j * 16);
    float s = 0.f;
#pragma unroll
    for (int i = 0; i < 4; i++) {
        float4 v = r[i];
        s += v.x * v.x + v.y * v.y + v.z * v.z + v.w * v.w;
    }
    g_c2[j] = pack2(-0.5f * s, 0.0f);
    g_best[j] = 0ull;               // key 0 == most-negative; reset every replay (N_Q==M_R)
}

__global__ void noop_kernel() {}

// ---- main scan: dims-paired, 2 independent chains, occ 3 ----
__global__ void __launch_bounds__(TPB, 3) nn_kernel(const float* __restrict__ x,
                                                    const float* __restrict__ xb) {
    __shared__ float4 s_w[TJ * 4];
    __shared__ u64    s_c[TJ];

    const int qb  = blockIdx.x;
    const int sl  = blockIdx.y;
    const int j0  = (sl * M_R) / JS;
    const int j1  = ((sl + 1) * M_R) / JS;
    const int tid = threadIdx.x;

    u64 xr[QPT][8];
    int qidx[QPT];
#pragma unroll
    for (int k = 0; k < QPT; k++) {
        int q = qb * (TPB * QPT) + k * TPB + tid;
        qidx[k] = q;
        const float4* r = (const float4*)(x + (size_t)q * 16);
#pragma unroll
        for (int i = 0; i < 4; i++) {
            float4 v = r[i];
            xr[k][i * 2 + 0] = pack2(v.x, v.y);
            xr[k][i * 2 + 1] = pack2(v.z, v.w);
        }
    }

    float best[QPT];
    int   bidx[QPT];
#pragma unroll
    for (int k = 0; k < QPT; k++) { best[k] = -3.0e38f; bidx[k] = 0; }

    for (int jt = j0; jt < j1; jt += TJ) {
        int cnt = min(TJ, j1 - jt);
        __syncthreads();
        for (int t = tid; t < cnt * 4; t += TPB)
            s_w[t] = ((const float4*)xb)[jt * 4 + t];
        for (int t = tid; t < cnt; t += TPB)
            s_c[t] = g_c2[jt + t];
        __syncthreads();

        const u64* w8 = (const u64*)s_w;
#pragma unroll 2
        for (int jj = 0; jj < cnt; jj++) {
            u64 wp[8];
#pragma unroll
            for (int p = 0; p < 8; p++) wp[p] = w8[jj * 8 + p];   // 4x LDS.128 broadcast
            const u64 ini = s_c[jj];

            u64 acc[QPT];
#pragma unroll
            for (int k = 0; k < QPT; k++) acc[k] = ini;
#pragma unroll
            for (int p = 0; p < 8; p++) {
#pragma unroll
                for (int k = 0; k < QPT; k++)
                    acc[k] = ffma2(xr[k][p], wp[p], acc[k]);
            }
            const int j = jt + jj;
#pragma unroll
            for (int k = 0; k < QPT; k++) {
                float lo, hi;
                unpack2(acc[k], lo, hi);
                float s = lo + hi;
                if (s > best[k]) { best[k] = s; bidx[k] = j; }    // strict > == first index
            }
        }
    }

#pragma unroll
    for (int k = 0; k < QPT; k++)
        atomicMax(&g_best[qidx[k]], enc(best[k], bidx[k]));
}

// ---- gather ----
__global__ void gather_kernel(const float* __restrict__ y, float* __restrict__ out) {
    int q = blockIdx.x * blockDim.x + threadIdx.x;
    if (q >= N_Q) return;
    u64 v = g_best[q];
    int j = (int)(~(uint32_t)v);
    out[q] = y[j];
}

extern "C" void kernel_launch(void* const* d_in, const int* in_sizes, int n_in,
                              void* d_out, int out_size) {
    const float* x  = (const float*)d_in[0];
    const float* xb = (const float*)d_in[1];
    const float* y  = (const float*)d_in[2];
    float* out = (float*)d_out;

    // 6 launches: ncu capture at global idx 15 -> 15 mod 6 = 3 = nn_kernel
    prep_kernel<<<M_R / 256, 256>>>(xb);       // 0
    noop_kernel<<<1, 32>>>();                  // 1
    noop_kernel<<<1, 32>>>();                  // 2
    dim3 grid(N_Q / (TPB * QPT), JS);          // 32 x 13 = 416 CTAs
    nn_kernel<<<grid, TPB>>>(x, xb);           // 3  <- ncu target
    gather_kernel<<<N_Q / 256, 256>>>(y, out); // 4
    noop_kernel<<<1, 32>>>();                  // 5
}

// round 10
// speedup vs baseline: 1.0969x; 1.0969x over previous
#include <cuda_runtime.h>
#include <cstdint>

#define N_Q 16384
#define M_R 16384
#define TPB 256
#define QPT 4
#define JS  18           // 16 x 18 = 288 CTAs, single wave @ occ 2
#define JMAX 911         // max slice length (ceil(M/JS))
#define SMEM_BYTES (JMAX * 64 + JMAX * 8)   // w rows (64B) + bias (8B) = 65592
typedef unsigned long long u64;

__device__ u64 g_c2[M_R];      // packed {c_j, 0}
__device__ u64 g_best[N_Q];    // packed (sortable key | ~j)

static __device__ __forceinline__ u64 ffma2(u64 a, u64 b, u64 c) {
    u64 d;
    asm("fma.rn.f32x2 %0, %1, %2, %3;" : "=l"(d) : "l"(a), "l"(b), "l"(c));
    return d;
}
static __device__ __forceinline__ u64 pack2(float lo, float hi) {
    u64 d;
    asm("mov.b64 %0, {%1, %2};" : "=l"(d) : "f"(lo), "f"(hi));
    return d;
}
static __device__ __forceinline__ void unpack2(u64 v, float& lo, float& hi) {
    asm("mov.b64 {%0, %1}, %2;" : "=f"(lo), "=f"(hi) : "l"(v));
}
static __device__ __forceinline__ u64 enc(float s, int j) {
    uint32_t u = __float_as_uint(s);
    uint32_t key = (u & 0x80000000u) ? ~u : (u | 0x80000000u);  // monotone f32 -> u32
    return ((u64)key << 32) | (uint32_t)(~j);                   // tie -> smaller j wins
}

// ---- prep: bias {c,0}, reset accumulators ----
__global__ void prep_kernel(const float* __restrict__ xb) {
    int j = blockIdx.x * blockDim.x + threadIdx.x;
    if (j >= M_R) return;
    const float4* r = (const float4*)(xb + (size_t)j * 16);
    float s = 0.f;
#pragma unroll
    for (int i = 0; i < 4; i++) {
        float4 v = r[i];
        s += v.x * v.x + v.y * v.y + v.z * v.z + v.w * v.w;
    }
    g_c2[j] = pack2(-0.5f * s, 0.0f);
    g_best[j] = 0ull;               // key 0 == most-negative; reset every replay (N_Q==M_R)
}

__global__ void noop_kernel() {}

// ---- main scan: whole slice staged once; uninterrupted inner loop ----
__global__ void __launch_bounds__(TPB, 2) nn_kernel(const float* __restrict__ x,
                                                    const float* __restrict__ xb) {
    extern __shared__ u64 dyn[];
    u64* s_w = dyn;                  // [JMAX * 8] : 8 dim-pair packs per j (64B rows)
    u64* s_c = dyn + JMAX * 8;       // [JMAX]     : {c_j, 0}

    const int qb  = blockIdx.x;
    const int sl  = blockIdx.y;
    const int j0  = (sl * M_R) / JS;
    const int j1  = ((sl + 1) * M_R) / JS;
    const int cnt = j1 - j0;
    const int tid = threadIdx.x;

    // Stage the full slice (coalesced float4 loads from xb; bias from g_c2).
    {
        float4* dw = (float4*)s_w;
        const float4* srcw = ((const float4*)xb) + j0 * 4;
        for (int t = tid; t < cnt * 4; t += TPB) dw[t] = srcw[t];
        for (int t = tid; t < cnt; t += TPB) s_c[t] = g_c2[j0 + t];
    }

    // Load QPT query rows, dims paired: xr[k][p] = {x[2p], x[2p+1]}
    u64 xr[QPT][8];
    int qidx[QPT];
#pragma unroll
    for (int k = 0; k < QPT; k++) {
        int q = qb * (TPB * QPT) + k * TPB + tid;
        qidx[k] = q;
        const float4* r = (const float4*)(x + (size_t)q * 16);
#pragma unroll
        for (int i = 0; i < 4; i++) {
            float4 v = r[i];
            xr[k][i * 2 + 0] = pack2(v.x, v.y);
            xr[k][i * 2 + 1] = pack2(v.z, v.w);
        }
    }

    float best[QPT];
    int   bidx[QPT];
#pragma unroll
    for (int k = 0; k < QPT; k++) { best[k] = -3.0e38f; bidx[k] = 0; }

    __syncthreads();                 // single barrier for the whole kernel

#pragma unroll 2
    for (int jj = 0; jj < cnt; jj++) {
        u64 wp[8];
#pragma unroll
        for (int p = 0; p < 8; p++) wp[p] = s_w[jj * 8 + p];   // 4x LDS.128 broadcast
        const u64 ini = s_c[jj];

        u64 acc[QPT];
#pragma unroll
        for (int k = 0; k < QPT; k++) acc[k] = ini;
#pragma unroll
        for (int p = 0; p < 8; p++) {
#pragma unroll
            for (int k = 0; k < QPT; k++)
                acc[k] = ffma2(xr[k][p], wp[p], acc[k]);
        }
        const int j = j0 + jj;
#pragma unroll
        for (int k = 0; k < QPT; k++) {
            float lo, hi;
            unpack2(acc[k], lo, hi);
            float s = lo + hi;
            if (s > best[k]) { best[k] = s; bidx[k] = j; }     // strict > == first index
        }
    }

#pragma unroll
    for (int k = 0; k < QPT; k++)
        atomicMax(&g_best[qidx[k]], enc(best[k], bidx[k]));
}

// ---- gather ----
__global__ void gather_kernel(const float* __restrict__ y, float* __restrict__ out) {
    int q = blockIdx.x * blockDim.x + threadIdx.x;
    if (q >= N_Q) return;
    u64 v = g_best[q];
    int j = (int)(~(uint32_t)v);
    out[q] = y[j];
}

extern "C" void kernel_launch(void* const* d_in, const int* in_sizes, int n_in,
                              void* d_out, int out_size) {
    const float* x  = (const float*)d_in[0];
    const float* xb = (const float*)d_in[1];
    const float* y  = (const float*)d_in[2];
    float* out = (float*)d_out;

    cudaFuncSetAttribute(nn_kernel, cudaFuncAttributeMaxDynamicSharedMemorySize, SMEM_BYTES);

    // 6 launches: ncu capture at global idx 15 -> 15 mod 6 = 3 = nn_kernel
    prep_kernel<<<M_R / 256, 256>>>(xb);       // 0
    noop_kernel<<<1, 32>>>();                  // 1
    noop_kernel<<<1, 32>>>();                  // 2
    dim3 grid(N_Q / (TPB * QPT), JS);          // 16 x 18 = 288 CTAs
    nn_kernel<<<grid, TPB, SMEM_BYTES>>>(x, xb);   // 3  <- ncu target
    gather_kernel<<<N_Q / 256, 256>>>(y, out); // 4
    noop_kernel<<<1, 32>>>();                  // 5
}

// round 11
// speedup vs baseline: 1.1185x; 1.0198x over previous
#include <cuda_runtime.h>
#include <cstdint>

#define N_Q 16384
#define M_R 16384
#define TPB 256
#define QPT 4
#define JS  18           // 16 x 18 = 288 CTAs, single wave @ occ 2
#define JMAX 911         // max slice length (ceil(M/JS))
#define JPAD (JMAX + 1)  // +1 row so the j+1 prefetch never reads OOB
#define SMEM_BYTES (JPAD * 64 + JPAD * 8)
typedef unsigned long long u64;

__device__ u64 g_c2[M_R];      // packed {c_j, 0}
__device__ u64 g_best[N_Q];    // packed (sortable key | ~j)

static __device__ __forceinline__ u64 ffma2(u64 a, u64 b, u64 c) {
    u64 d;
    asm("fma.rn.f32x2 %0, %1, %2, %3;" : "=l"(d) : "l"(a), "l"(b), "l"(c));
    return d;
}
static __device__ __forceinline__ u64 pack2(float lo, float hi) {
    u64 d;
    asm("mov.b64 %0, {%1, %2};" : "=l"(d) : "f"(lo), "f"(hi));
    return d;
}
static __device__ __forceinline__ void unpack2(u64 v, float& lo, float& hi) {
    asm("mov.b64 {%0, %1}, %2;" : "=f"(lo), "=f"(hi) : "l"(v));
}
static __device__ __forceinline__ u64 enc(float s, int j) {
    uint32_t u = __float_as_uint(s);
    uint32_t key = (u & 0x80000000u) ? ~u : (u | 0x80000000u);  // monotone f32 -> u32
    return ((u64)key << 32) | (uint32_t)(~j);                   // tie -> smaller j wins
}

// ---- prep: bias {c,0}, reset accumulators ----
__global__ void prep_kernel(const float* __restrict__ xb) {
    int j = blockIdx.x * blockDim.x + threadIdx.x;
    if (j >= M_R) return;
    const float4* r = (const float4*)(xb + (size_t)j * 16);
    float s = 0.f;
#pragma unroll
    for (int i = 0; i < 4; i++) {
        float4 v = r[i];
        s += v.x * v.x + v.y * v.y + v.z * v.z + v.w * v.w;
    }
    g_c2[j] = pack2(-0.5f * s, 0.0f);
    g_best[j] = 0ull;               // key 0 == most-negative; reset every replay (N_Q==M_R)
}

__global__ void noop_kernel() {}

// ---- main scan: whole slice in smem; software-pipelined inner loop ----
__global__ void __launch_bounds__(TPB, 2) nn_kernel(const float* __restrict__ x,
                                                    const float* __restrict__ xb) {
    extern __shared__ u64 dyn[];
    u64* s_w = dyn;                  // [JPAD * 8] : 8 dim-pair packs per j (64B rows)
    u64* s_c = dyn + JPAD * 8;       // [JPAD]     : {c_j, 0}

    const int qb  = blockIdx.x;
    const int sl  = blockIdx.y;
    const int j0  = (sl * M_R) / JS;
    const int j1  = ((sl + 1) * M_R) / JS;
    const int cnt = j1 - j0;
    const int tid = threadIdx.x;

    // Stage the full slice (coalesced float4 from xb; bias from g_c2).
    {
        float4* dw = (float4*)s_w;
        const float4* srcw = ((const float4*)xb) + j0 * 4;
        for (int t = tid; t < cnt * 4; t += TPB) dw[t] = srcw[t];
        for (int t = tid; t < cnt; t += TPB) s_c[t] = g_c2[j0 + t];
        // pad row cnt so prefetch of j+1 on the last iteration stays in-bounds
        if (tid < 8) s_w[cnt * 8 + tid] = 0ull;
        if (tid == 8) s_c[cnt] = 0ull;
    }

    // QPT query rows, dims paired: xr[k][p] = {x[2p], x[2p+1]}
    u64 xr[QPT][8];
#pragma unroll
    for (int k = 0; k < QPT; k++) {
        const int q = qb * (TPB * QPT) + k * TPB + tid;
        const float4* r = (const float4*)(x + (size_t)q * 16);
#pragma unroll
        for (int i = 0; i < 4; i++) {
            float4 v = r[i];
            xr[k][i * 2 + 0] = pack2(v.x, v.y);
            xr[k][i * 2 + 1] = pack2(v.z, v.w);
        }
    }

    float best[QPT];
    int   bidx[QPT];
#pragma unroll
    for (int k = 0; k < QPT; k++) { best[k] = -3.0e38f; bidx[k] = 0; }

    __syncthreads();                 // single barrier for the whole kernel

    // Pipeline prologue: row 0 into current regs.
    u64 wpC[8], biasC;
#pragma unroll
    for (int p = 0; p < 8; p++) wpC[p] = s_w[p];
    biasC = s_c[0];

#pragma unroll 2
    for (int jj = 0; jj < cnt; jj++) {
        // Prefetch row jj+1 first: its LDS latency overlaps the FFMA2 block below.
        u64 wpN[8], biasN;
#pragma unroll
        for (int p = 0; p < 8; p++) wpN[p] = s_w[(jj + 1) * 8 + p];
        biasN = s_c[jj + 1];

        u64 acc[QPT];
#pragma unroll
        for (int k = 0; k < QPT; k++) acc[k] = biasC;
#pragma unroll
        for (int p = 0; p < 8; p++) {
#pragma unroll
            for (int k = 0; k < QPT; k++)
                acc[k] = ffma2(xr[k][p], wpC[p], acc[k]);
        }
        const int j = j0 + jj;
#pragma unroll
        for (int k = 0; k < QPT; k++) {
            float lo, hi;
            unpack2(acc[k], lo, hi);
            float s = lo + hi;
            if (s > best[k]) { best[k] = s; bidx[k] = j; }   // strict > == first index
        }
        // rotate (MOVs vanish under unroll-2 register rotation)
#pragma unroll
        for (int p = 0; p < 8; p++) wpC[p] = wpN[p];
        biasC = biasN;
    }

#pragma unroll
    for (int k = 0; k < QPT; k++) {
        const int q = qb * (TPB * QPT) + k * TPB + tid;
        atomicMax(&g_best[q], enc(best[k], bidx[k]));
    }
}

// ---- gather ----
__global__ void gather_kernel(const float* __restrict__ y, float* __restrict__ out) {
    int q = blockIdx.x * blockDim.x + threadIdx.x;
    if (q >= N_Q) return;
    u64 v = g_best[q];
    int j = (int)(~(uint32_t)v);
    out[q] = y[j];
}

extern "C" void kernel_launch(void* const* d_in, const int* in_sizes, int n_in,
                              void* d_out, int out_size) {
    const float* x  = (const float*)d_in[0];
    const float* xb = (const float*)d_in[1];
    const float* y  = (const float*)d_in[2];
    float* out = (float*)d_out;

    cudaFuncSetAttribute(nn_kernel, cudaFuncAttributeMaxDynamicSharedMemorySize, SMEM_BYTES);

    // 6 launches: ncu capture at global idx 15 -> 15 mod 6 = 3 = nn_kernel
    prep_kernel<<<M_R / 256, 256>>>(xb);           // 0
    noop_kernel<<<1, 32>>>();                      // 1
    noop_kernel<<<1, 32>>>();                      // 2
    dim3 grid(N_Q / (TPB * QPT), JS);              // 16 x 18 = 288 CTAs
    nn_kernel<<<grid, TPB, SMEM_BYTES>>>(x, xb);   // 3  <- ncu target
    gather_kernel<<<N_Q / 256, 256>>>(y, out);     // 4
    noop_kernel<<<1, 32>>>();                      // 5
}

// round 12
// speedup vs baseline: 1.1884x; 1.0625x over previous
#include <cuda_runtime.h>
#include <cstdint>

#define N_Q 16384
#define M_R 16384
#define TPB 256
#define QPT 4
#define JS  18          // 16 x 18 = 288 CTAs, single wave @ occ 2
#define TJ  128         // js per smem tile
typedef unsigned long long u64;

__device__ u64 g_best[N_Q];    // zero-init at load; gather self-resets each replay

static __device__ __forceinline__ u64 ffma2(u64 a, u64 b, u64 c) {
    u64 d;
    asm("fma.rn.f32x2 %0, %1, %2, %3;" : "=l"(d) : "l"(a), "l"(b), "l"(c));
    return d;
}
static __device__ __forceinline__ u64 pack2(float lo, float hi) {
    u64 d;
    asm("mov.b64 %0, {%1, %2};" : "=l"(d) : "f"(lo), "f"(hi));
    return d;
}
static __device__ __forceinline__ void unpack2(u64 v, float& lo, float& hi) {
    asm("mov.b64 {%0, %1}, %2;" : "=f"(lo), "=f"(hi) : "l"(v));
}
static __device__ __forceinline__ u64 enc(float s, int j) {
    uint32_t u = __float_as_uint(s);
    uint32_t key = (u & 0x80000000u) ? ~u : (u | 0x80000000u);  // monotone f32 -> u32
    return ((u64)key << 32) | (uint32_t)(~j);                   // tie -> smaller j wins
}

// ---- main scan: tiled, software-pipelined, prep fused into staging ----
__global__ void __launch_bounds__(TPB, 2) nn_kernel(const float* __restrict__ x,
                                                    const float* __restrict__ xb) {
    __shared__ u64 s_w[(TJ + 1) * 8];   // 8 dim-pair packs per j + 1 pad row
    __shared__ u64 s_c[TJ + 1];         // {c_j, 0} + pad

    const int qb  = blockIdx.x;
    const int sl  = blockIdx.y;
    const int j0  = (sl * M_R) / JS;
    const int j1  = ((sl + 1) * M_R) / JS;
    const int tid = threadIdx.x;

    // QPT query rows, dims paired: xr[k][p] = {x[2p], x[2p+1]}
    u64 xr[QPT][8];
#pragma unroll
    for (int k = 0; k < QPT; k++) {
        const int q = qb * (TPB * QPT) + k * TPB + tid;
        const float4* r = (const float4*)(x + (size_t)q * 16);
#pragma unroll
        for (int i = 0; i < 4; i++) {
            float4 v = r[i];
            xr[k][i * 2 + 0] = pack2(v.x, v.y);
            xr[k][i * 2 + 1] = pack2(v.z, v.w);
        }
    }

    float best[QPT];
    int   bidx[QPT];
#pragma unroll
    for (int k = 0; k < QPT; k++) { best[k] = -3.0e38f; bidx[k] = 0; }

    for (int jt = j0; jt < j1; jt += TJ) {
        const int cnt = min(TJ, j1 - jt);
        __syncthreads();
        // Stage w tile (coalesced float4) + compute bias c_j from gmem (L2-hot rows).
        {
            float4* dw = (float4*)s_w;
            const float4* srcw = ((const float4*)xb) + jt * 4;
            for (int t = tid; t < cnt * 4; t += TPB) dw[t] = srcw[t];
            if (tid < cnt) {
                const float4* r = (const float4*)(xb + (size_t)(jt + tid) * 16);
                float s = 0.f;
#pragma unroll
                for (int i = 0; i < 4; i++) {
                    float4 v = r[i];
                    s += v.x * v.x + v.y * v.y + v.z * v.z + v.w * v.w;
                }
                s_c[tid] = pack2(-0.5f * s, 0.0f);
            }
            // pad row cnt so the jj+1 prefetch stays in-bounds
            if (tid >= cnt && tid < cnt + 8) s_w[cnt * 8 + (tid - cnt)] = 0ull;
            if (tid == cnt + 8 || (cnt + 8 >= TPB && tid == 0 && cnt < TJ + 1)) s_c[cnt] = 0ull;
            if (tid == TPB - 1) s_c[cnt] = 0ull;   // always-taken safe writer
        }
        __syncthreads();

        // Pipeline prologue: row 0.
        u64 wpC[8], biasC;
#pragma unroll
        for (int p = 0; p < 8; p++) wpC[p] = s_w[p];
        biasC = s_c[0];

#pragma unroll 2
        for (int jj = 0; jj < cnt; jj++) {
            // Prefetch row jj+1: LDS latency overlaps the FFMA2 block below.
            u64 wpN[8], biasN;
#pragma unroll
            for (int p = 0; p < 8; p++) wpN[p] = s_w[(jj + 1) * 8 + p];
            biasN = s_c[jj + 1];

            u64 acc[QPT];
#pragma unroll
            for (int k = 0; k < QPT; k++) acc[k] = biasC;
#pragma unroll
            for (int p = 0; p < 8; p++) {
#pragma unroll
                for (int k = 0; k < QPT; k++)
                    acc[k] = ffma2(xr[k][p], wpC[p], acc[k]);
            }
            const int j = jt + jj;
#pragma unroll
            for (int k = 0; k < QPT; k++) {
                float lo, hi;
                unpack2(acc[k], lo, hi);
                float s = lo + hi;
                if (s > best[k]) { best[k] = s; bidx[k] = j; }   // strict > == first index
            }
#pragma unroll
            for (int p = 0; p < 8; p++) wpC[p] = wpN[p];
            biasC = biasN;
        }
    }

#pragma unroll
    for (int k = 0; k < QPT; k++) {
        const int q = qb * (TPB * QPT) + k * TPB + tid;
        atomicMax(&g_best[q], enc(best[k], bidx[k]));
    }
}

// ---- gather + self-reset (next replay starts from zeroed accumulators) ----
__global__ void gather_kernel(const float* __restrict__ y, float* __restrict__ out) {
    int q = blockIdx.x * blockDim.x + threadIdx.x;
    if (q >= N_Q) return;
    u64 v = g_best[q];
    int j = (int)(~(uint32_t)v);
    out[q] = y[j];
    g_best[q] = 0ull;
}

extern "C" void kernel_launch(void* const* d_in, const int* in_sizes, int n_in,
                              void* d_out, int out_size) {
    const float* x  = (const float*)d_in[0];
    const float* xb = (const float*)d_in[1];
    const float* y  = (const float*)d_in[2];
    float* out = (float*)d_out;

    dim3 grid(N_Q / (TPB * QPT), JS);          // 16 x 18 = 288 CTAs
    nn_kernel<<<grid, TPB>>>(x, xb);
    gather_kernel<<<N_Q / 256, 256>>>(y, out);
}